// round 3
// baseline (speedup 1.0000x reference)
#include <cuda_runtime.h>
#include <math.h>

#define BATCH 2048
#define EPS 1e-5f

// ---------------- device scratch (no allocation allowed) ----------------
__device__ __align__(16) unsigned g_w1p[512 * 128];   // fc1 weight bits [oc][128 words]
__device__ __align__(16) unsigned g_w2p[256 * 16];    // fc2 weight bits [oc][16 words]
__device__ unsigned g_w2bits[64 * 9];                 // conv2 weight bits [oc][9 taps] over 32 in-ch
__device__ unsigned g_act1[BATCH * 256];              // post conv1/pool/bn1/sign: [b][y*16+x] 32-ch mask
__device__ __align__(16) unsigned g_act2[BATCH * 128];// post conv2/pool/bn2/sign, fc1 bit order
__device__ __align__(16) unsigned g_act3[BATCH * 16]; // post fc1/bn3/sign: [b][16 words]

// ---------------- weight bit packing ----------------
__global__ void k_pack(const float* __restrict__ fc1w,
                       const float* __restrict__ fc2w,
                       const float* __restrict__ c2w) {
    const int N1 = 512 * 4096;      // fc1 bits
    const int N2 = 256 * 512;       // fc2 bits
    const int N3 = 64 * 9 * 32;     // conv2 bits
    int t = blockIdx.x * blockDim.x + threadIdx.x;
    bool bit = false;
    unsigned* dst = 0;
    int word = 0;
    if (t < N1) {
        bit = fc1w[t] > 0.0f;
        dst = g_w1p; word = t >> 5;
    } else if (t < N1 + N2) {
        int u = t - N1;
        bit = fc2w[u] > 0.0f;
        dst = g_w2p; word = u >> 5;
    } else if (t < N1 + N2 + N3) {
        int u = t - (N1 + N2);
        int c = u & 31;
        int w9 = u >> 5;            // 0..575
        int k = w9 % 9, oc = w9 / 9;
        bit = c2w[oc * 288 + c * 9 + k] > 0.0f;
        dst = g_w2bits; word = w9;
    } else {
        return;                      // never happens: exact grid
    }
    unsigned m = __ballot_sync(0xffffffffu, bit);
    if ((t & 31) == 0) dst[word] = m;
}

// ---------------- conv1 + maxpool + bn1 + sign -> bitmask ----------------
// One block per image, 256 threads = 16x16 pooled positions.
__global__ __launch_bounds__(256, 1) void k_conv1(
    const float* __restrict__ x, const float* __restrict__ w,
    const float* __restrict__ bias, const float* __restrict__ g,
    const float* __restrict__ bb, const float* __restrict__ mn,
    const float* __restrict__ vr)
{
    __shared__ float img[3][34][34];   // zero-padded input
    __shared__ float sw[32][27];       // sign(w) as +-1.0f
    __shared__ float sb[32], st[32];
    int b = blockIdx.x, tid = threadIdx.x;

    float* fi = &img[0][0][0];
    for (int i = tid; i < 3 * 34 * 34; i += 256) fi[i] = 0.0f;
    __syncthreads();
    const float* xb = x + (size_t)b * 3 * 32 * 32;
    for (int i = tid; i < 3 * 32 * 32; i += 256) {
        int c = i >> 10, r = (i >> 5) & 31, cc = i & 31;
        img[c][r + 1][cc + 1] = xb[i];
    }
    for (int i = tid; i < 32 * 27; i += 256)
        sw[i / 27][i % 27] = (w[i] > 0.0f) ? 1.0f : -1.0f;
    if (tid < 32) {
        sb[tid] = bias[tid];
        st[tid] = mn[tid] - bb[tid] * sqrtf(vr[tid] + EPS) / g[tid];
    }
    __syncthreads();

    int pi = tid >> 4, pj = tid & 15;
    int y0 = 2 * pi, x0 = 2 * pj;      // padded coords of top-left tap row/col
    float xr[3][4][4];
    #pragma unroll
    for (int c = 0; c < 3; c++)
        #pragma unroll
        for (int r = 0; r < 4; r++)
            #pragma unroll
            for (int q = 0; q < 4; q++)
                xr[c][r][q] = img[c][y0 + r][x0 + q];

    unsigned bits = 0;
    for (int oc = 0; oc < 32; oc++) {
        float a0 = 0.f, a1 = 0.f, a2 = 0.f, a3 = 0.f;
        #pragma unroll
        for (int c = 0; c < 3; c++)
            #pragma unroll
            for (int dy = 0; dy < 3; dy++)
                #pragma unroll
                for (int dx = 0; dx < 3; dx++) {
                    float wv = sw[oc][c * 9 + dy * 3 + dx];
                    a0 += wv * xr[c][dy][dx];
                    a1 += wv * xr[c][dy][dx + 1];
                    a2 += wv * xr[c][dy + 1][dx];
                    a3 += wv * xr[c][dy + 1][dx + 1];
                }
        float mx = fmaxf(fmaxf(a0, a1), fmaxf(a2, a3)) + sb[oc];
        if (mx > st[oc]) bits |= (1u << oc);
    }
    g_act1[b * 256 + tid] = bits;
}

// ---------------- conv2 (XNOR) + maxpool + bn2 + sign -> fc1-order bits ----------------
// One block per image: 256 threads = 64 pooled positions x 4 oc-groups of 16.
__global__ __launch_bounds__(256, 1) void k_conv2(
    const float* __restrict__ bias, const float* __restrict__ g,
    const float* __restrict__ bb, const float* __restrict__ mn,
    const float* __restrict__ vr)
{
    __shared__ unsigned sin_[18][18];
    __shared__ unsigned swb[64 * 9];
    __shared__ float sb[64], st[64];
    int b = blockIdx.x, tid = threadIdx.x;

    unsigned* si = &sin_[0][0];
    for (int i = tid; i < 18 * 18; i += 256) si[i] = 0u;
    __syncthreads();
    {
        int i = tid;                   // 256 = 16x16 exactly
        int r = i >> 4, c = i & 15;
        sin_[r + 1][c + 1] = g_act1[b * 256 + i];
    }
    for (int i = tid; i < 576; i += 256) swb[i] = g_w2bits[i];
    if (tid < 64) {
        sb[tid] = bias[tid];
        st[tid] = mn[tid] - bb[tid] * sqrtf(vr[tid] + EPS) / g[tid];
    }
    __syncthreads();

    int p = tid & 63;                  // pooled position 0..63
    int gq = tid >> 6;                 // oc group 0..3
    int pi = p >> 3, pj = p & 7;
    int y0 = 2 * pi, x0 = 2 * pj;      // padded coords

    unsigned a[4][4], mk[4][4];
    #pragma unroll
    for (int r = 0; r < 4; r++)
        #pragma unroll
        for (int q = 0; q < 4; q++) {
            a[r][q] = sin_[y0 + r][x0 + q];
            int rr = y0 + r - 1, cc = x0 + q - 1;
            mk[r][q] = (rr >= 0 && rr < 16 && cc >= 0 && cc < 16) ? 0xffffffffu : 0u;
        }
    int nvs[2][2];
    #pragma unroll
    for (int u = 0; u < 2; u++)
        #pragma unroll
        for (int vq = 0; vq < 2; vq++) {
            int cnt = 0;
            #pragma unroll
            for (int dy = 0; dy < 3; dy++)
                #pragma unroll
                for (int dx = 0; dx < 3; dx++)
                    cnt += (mk[u + dy][vq + dx] != 0u);
            nvs[u][vq] = cnt * 32;
        }

    for (int j = 0; j < 16; j++) {
        int oc = gq * 16 + j;
        const unsigned* wp = &swb[oc * 9];
        int mdot = -1000000;
        #pragma unroll
        for (int u = 0; u < 2; u++)
            #pragma unroll
            for (int vq = 0; vq < 2; vq++) {
                int acc = 0;
                #pragma unroll
                for (int dy = 0; dy < 3; dy++)
                    #pragma unroll
                    for (int dx = 0; dx < 3; dx++)
                        acc += __popc((a[u + dy][vq + dx] ^ wp[dy * 3 + dx]) & mk[u + dy][vq + dx]);
                int d = nvs[u][vq] - 2 * acc;
                mdot = max(mdot, d);
            }
        bool bit = ((float)mdot + sb[oc]) > st[oc];
        unsigned bal = __ballot_sync(0xffffffffu, bit);
        if ((tid & 31) == 0) {
            int wrd = oc * 2 + (p >> 5);     // fc1 bit index = oc*64 + p
            g_act2[b * 128 + wrd] = bal;
        }
    }
}

// ---------------- fc1 (XNOR 4096-bit) + bn3 + sign ----------------
// Block: 8 samples x 512 ocs, 512 threads (one per oc).
__global__ __launch_bounds__(512, 1) void k_fc1(
    const float* __restrict__ bias, const float* __restrict__ g,
    const float* __restrict__ bb, const float* __restrict__ mn,
    const float* __restrict__ vr)
{
    __shared__ uint4 sa[8][32];
    int b0 = blockIdx.x * 8, tid = threadIdx.x;
    if (tid < 256) {
        int s = tid >> 5, k = tid & 31;
        const uint4* src = reinterpret_cast<const uint4*>(g_act2 + (b0 + s) * 128);
        sa[s][k] = src[k];
    }
    __syncthreads();

    int oc = tid;
    const uint4* wp = reinterpret_cast<const uint4*>(g_w1p + oc * 128);
    int acc[8] = {0, 0, 0, 0, 0, 0, 0, 0};
    #pragma unroll 4
    for (int k = 0; k < 32; k++) {
        uint4 w = wp[k];
        #pragma unroll
        for (int s = 0; s < 8; s++) {
            uint4 aa = sa[s][k];
            acc[s] += __popc(aa.x ^ w.x) + __popc(aa.y ^ w.y)
                    + __popc(aa.z ^ w.z) + __popc(aa.w ^ w.w);
        }
    }
    float bi = bias[oc];
    float th = mn[oc] - bb[oc] * sqrtf(vr[oc] + EPS) / g[oc];
    #pragma unroll
    for (int s = 0; s < 8; s++) {
        bool bit = ((float)(4096 - 2 * acc[s]) + bi) > th;
        unsigned bal = __ballot_sync(0xffffffffu, bit);
        if ((tid & 31) == 0) g_act3[(b0 + s) * 16 + (oc >> 5)] = bal;
    }
}

// ---------------- fc2 + bn4 + clip + fc3 + log_softmax ----------------
// One block per sample, 256 threads (one per fc2 oc).
__global__ __launch_bounds__(256, 1) void k_head(
    const float* __restrict__ fc2b, const float* __restrict__ g4,
    const float* __restrict__ b4, const float* __restrict__ m4,
    const float* __restrict__ v4, const float* __restrict__ fc3w,
    const float* __restrict__ fc3b, float* __restrict__ out)
{
    __shared__ __align__(16) unsigned a3[16];
    __shared__ float wred[8][10];
    __shared__ float lg[10];
    __shared__ float mx_s, ls_s;
    int b = blockIdx.x, tid = threadIdx.x;
    if (tid < 16) a3[tid] = g_act3[b * 16 + tid];
    __syncthreads();

    int o = tid;
    const uint4* wp = reinterpret_cast<const uint4*>(g_w2p + o * 16);
    const uint4* ap = reinterpret_cast<const uint4*>(a3);
    int acc = 0;
    #pragma unroll
    for (int k = 0; k < 4; k++) {
        uint4 w = wp[k];
        uint4 aa = ap[k];
        acc += __popc(aa.x ^ w.x) + __popc(aa.y ^ w.y)
             + __popc(aa.z ^ w.z) + __popc(aa.w ^ w.w);
    }
    float y = (float)(512 - 2 * acc) + fc2b[o];
    float inv = g4[o] / sqrtf(v4[o] + EPS);
    float val = y * inv + (b4[o] - m4[o] * inv);
    val = fminf(1.0f, fmaxf(-1.0f, val));

    float p[10];
    #pragma unroll
    for (int j = 0; j < 10; j++) p[j] = val * fc3w[j * 256 + o];
    #pragma unroll
    for (int j = 0; j < 10; j++) {
        float t = p[j];
        #pragma unroll
        for (int off = 16; off; off >>= 1) t += __shfl_xor_sync(0xffffffffu, t, off);
        if ((tid & 31) == 0) wred[tid >> 5][j] = t;
    }
    __syncthreads();
    if (tid < 10) {
        float s = 0.0f;
        #pragma unroll
        for (int w2 = 0; w2 < 8; w2++) s += wred[w2][tid];
        lg[tid] = s + fc3b[tid];
    }
    __syncthreads();
    if (tid == 0) {
        float mx = lg[0];
        #pragma unroll
        for (int j = 1; j < 10; j++) mx = fmaxf(mx, lg[j]);
        float ssum = 0.0f;
        #pragma unroll
        for (int j = 0; j < 10; j++) ssum += expf(lg[j] - mx);
        mx_s = mx;
        ls_s = logf(ssum);
    }
    __syncthreads();
    if (tid < 10) out[b * 10 + tid] = lg[tid] - mx_s - ls_s;
}

// ---------------- launch ----------------
extern "C" void kernel_launch(void* const* d_in, const int* in_sizes, int n_in,
                              void* d_out, int out_size) {
    const float* x    = (const float*)d_in[0];
    const float* c1w  = (const float*)d_in[1];
    const float* c1b  = (const float*)d_in[2];
    const float* bn1g = (const float*)d_in[3];
    const float* bn1b = (const float*)d_in[4];
    const float* bn1m = (const float*)d_in[5];
    const float* bn1v = (const float*)d_in[6];
    const float* c2w  = (const float*)d_in[7];
    const float* c2b  = (const float*)d_in[8];
    const float* bn2g = (const float*)d_in[9];
    const float* bn2b = (const float*)d_in[10];
    const float* bn2m = (const float*)d_in[11];
    const float* bn2v = (const float*)d_in[12];
    const float* fc1w = (const float*)d_in[13];
    const float* fc1b = (const float*)d_in[14];
    const float* bn3g = (const float*)d_in[15];
    const float* bn3b = (const float*)d_in[16];
    const float* bn3m = (const float*)d_in[17];
    const float* bn3v = (const float*)d_in[18];
    const float* fc2w = (const float*)d_in[19];
    const float* fc2b = (const float*)d_in[20];
    const float* bn4g = (const float*)d_in[21];
    const float* bn4b = (const float*)d_in[22];
    const float* bn4m = (const float*)d_in[23];
    const float* bn4v = (const float*)d_in[24];
    const float* fc3w = (const float*)d_in[25];
    const float* fc3b = (const float*)d_in[26];
    float* out = (float*)d_out;

    // total pack threads = 512*4096 + 256*512 + 64*9*32 = 2246656 = 8776 * 256
    k_pack<<<8776, 256>>>(fc1w, fc2w, c2w);
    k_conv1<<<BATCH, 256>>>(x, c1w, c1b, bn1g, bn1b, bn1m, bn1v);
    k_conv2<<<BATCH, 256>>>(c2b, bn2g, bn2b, bn2m, bn2v);
    k_fc1<<<BATCH / 8, 512>>>(fc1b, bn3g, bn3b, bn3m, bn3v);
    k_head<<<BATCH, 256>>>(fc2b, bn4g, bn4b, bn4m, bn4v, fc3w, fc3b, out);
}

// round 4
// speedup vs baseline: 1.0132x; 1.0132x over previous
#include <cuda_runtime.h>
#include <math.h>

#define BATCH 2048
#define EPS 1e-5f

// ---------------- device scratch (no allocation allowed) ----------------
__device__ __align__(16) unsigned g_w1p[512 * 128];   // fc1 weight bits [oc][128 words]
__device__ __align__(16) unsigned g_w2p[256 * 16];    // fc2 weight bits [oc][16 words]
__device__ unsigned g_w2bits[64 * 9];                 // conv2 weight bits [oc][9 taps] over 32 in-ch
__device__ unsigned g_act1[BATCH * 256];              // post conv1/pool/bn1/sign: [b][y*16+x] 32-ch mask
__device__ __align__(16) unsigned g_act2[BATCH * 128];// post conv2/pool/bn2/sign, fc1 bit order
__device__ __align__(16) unsigned g_act3[BATCH * 16]; // post fc1/bn3/sign: [b][16 words]

// ---------------- f32x2 packed helpers (Blackwell FFMA2, PTX-only) ----------------
__device__ __forceinline__ unsigned long long pack2(float lo, float hi) {
    unsigned long long r;
    asm("mov.b64 %0, {%1, %2};" : "=l"(r) : "f"(lo), "f"(hi));
    return r;
}
__device__ __forceinline__ void unpack2(unsigned long long v, float& lo, float& hi) {
    asm("mov.b64 {%0, %1}, %2;" : "=f"(lo), "=f"(hi) : "l"(v));
}
__device__ __forceinline__ unsigned long long fma2(unsigned long long a,
                                                   unsigned long long b,
                                                   unsigned long long c) {
    unsigned long long d;
    asm("fma.rn.f32x2 %0, %1, %2, %3;" : "=l"(d) : "l"(a), "l"(b), "l"(c));
    return d;
}

// ---------------- weight bit packing ----------------
__global__ void k_pack(const float* __restrict__ fc1w,
                       const float* __restrict__ fc2w,
                       const float* __restrict__ c2w) {
    const int N1 = 512 * 4096;      // fc1 bits
    const int N2 = 256 * 512;       // fc2 bits
    const int N3 = 64 * 9 * 32;     // conv2 bits
    int t = blockIdx.x * blockDim.x + threadIdx.x;
    bool bit = false;
    unsigned* dst = 0;
    int word = 0;
    if (t < N1) {
        bit = fc1w[t] > 0.0f;
        dst = g_w1p; word = t >> 5;
    } else if (t < N1 + N2) {
        int u = t - N1;
        bit = fc2w[u] > 0.0f;
        dst = g_w2p; word = u >> 5;
    } else if (t < N1 + N2 + N3) {
        int u = t - (N1 + N2);
        int c = u & 31;
        int w9 = u >> 5;            // 0..575
        int k = w9 % 9, oc = w9 / 9;
        bit = c2w[oc * 288 + c * 9 + k] > 0.0f;
        dst = g_w2bits; word = w9;
    } else {
        return;                      // never happens: exact grid
    }
    unsigned m = __ballot_sync(0xffffffffu, bit);
    if ((t & 31) == 0) dst[word] = m;
}

// ---------------- conv1 + maxpool + bn1 + sign -> bitmask ----------------
// One block per image, 256 threads = 16x16 pooled positions.
// FFMA2: two conv outputs per packed op. Rounding per lane identical to scalar FFMA.
__global__ __launch_bounds__(256, 2) void k_conv1(
    const float* __restrict__ x, const float* __restrict__ w,
    const float* __restrict__ bias, const float* __restrict__ g,
    const float* __restrict__ bb, const float* __restrict__ mn,
    const float* __restrict__ vr)
{
    __shared__ float img[3][34][34];              // zero-padded input
    __shared__ unsigned long long sw2[32 * 27];   // sign(w) duplicated in both lanes
    __shared__ float sb[32], st[32];
    int b = blockIdx.x, tid = threadIdx.x;

    float* fi = &img[0][0][0];
    for (int i = tid; i < 3 * 34 * 34; i += 256) fi[i] = 0.0f;
    __syncthreads();
    const float* xb = x + (size_t)b * 3 * 32 * 32;
    for (int i = tid; i < 3 * 32 * 32; i += 256) {
        int c = i >> 10, r = (i >> 5) & 31, cc = i & 31;
        img[c][r + 1][cc + 1] = xb[i];
    }
    for (int i = tid; i < 32 * 27; i += 256) {
        float v = (w[i] > 0.0f) ? 1.0f : -1.0f;
        sw2[i] = pack2(v, v);
    }
    if (tid < 32) {
        sb[tid] = bias[tid];
        st[tid] = mn[tid] - bb[tid] * sqrtf(vr[tid] + EPS) / g[tid];
    }
    __syncthreads();

    int pi = tid >> 4, pj = tid & 15;
    int y0 = 2 * pi, x0 = 2 * pj;      // padded coords of top-left tap
    // packed horizontal pairs: pr[c][r][q] = (x[r][q], x[r][q+1]),  q=0..2
    unsigned long long pr[3][4][3];
    #pragma unroll
    for (int c = 0; c < 3; c++)
        #pragma unroll
        for (int r = 0; r < 4; r++) {
            float v0 = img[c][y0 + r][x0 + 0];
            float v1 = img[c][y0 + r][x0 + 1];
            float v2 = img[c][y0 + r][x0 + 2];
            float v3 = img[c][y0 + r][x0 + 3];
            pr[c][r][0] = pack2(v0, v1);
            pr[c][r][1] = pack2(v1, v2);
            pr[c][r][2] = pack2(v2, v3);
        }

    unsigned bits = 0;
    for (int oc = 0; oc < 32; oc++) {
        unsigned long long acc01 = 0ULL, acc23 = 0ULL;   // (0.0f, 0.0f) pairs
        const unsigned long long* wp = &sw2[oc * 27];
        #pragma unroll
        for (int c = 0; c < 3; c++)
            #pragma unroll
            for (int dy = 0; dy < 3; dy++)
                #pragma unroll
                for (int dx = 0; dx < 3; dx++) {
                    unsigned long long w2 = wp[c * 9 + dy * 3 + dx];
                    acc01 = fma2(pr[c][dy][dx], w2, acc01);
                    acc23 = fma2(pr[c][dy + 1][dx], w2, acc23);
                }
        float a0, a1, a2, a3;
        unpack2(acc01, a0, a1);
        unpack2(acc23, a2, a3);
        float mx = fmaxf(fmaxf(a0, a1), fmaxf(a2, a3)) + sb[oc];
        if (mx > st[oc]) bits |= (1u << oc);
    }
    g_act1[b * 256 + tid] = bits;
}

// ---------------- conv2 (XNOR) + maxpool + bn2 + sign -> fc1-order bits ----------------
// One block per image: 256 threads = 64 pooled positions x 4 oc-groups of 16.
// Padding handled algebraically: halo words are 0, so each invalid tap adds
// exactly popc(w_tap) to the xor-popc sum; subtract precomputed row/col sums.
__global__ __launch_bounds__(256, 2) void k_conv2(
    const float* __restrict__ bias, const float* __restrict__ g,
    const float* __restrict__ bb, const float* __restrict__ mn,
    const float* __restrict__ vr)
{
    __shared__ unsigned sin_[18][18];
    __shared__ unsigned swb[64 * 9];
    __shared__ int wpcS[64 * 9];     // popc of each weight tap
    __shared__ int wr[64 * 3];       // per-oc row sums of tap popcs
    __shared__ int wc[64 * 3];       // per-oc col sums of tap popcs
    __shared__ float sb[64], st[64];
    int b = blockIdx.x, tid = threadIdx.x;

    unsigned* si = &sin_[0][0];
    for (int i = tid; i < 18 * 18; i += 256) si[i] = 0u;
    for (int i = tid; i < 576; i += 256) {
        unsigned wv = g_w2bits[i];
        swb[i] = wv;
        wpcS[i] = __popc(wv);
    }
    if (tid < 64) {
        sb[tid] = bias[tid];
        st[tid] = mn[tid] - bb[tid] * sqrtf(vr[tid] + EPS) / g[tid];
    }
    __syncthreads();
    {
        int i = tid;                   // 256 = 16x16 exactly
        int r = i >> 4, c = i & 15;
        sin_[r + 1][c + 1] = g_act1[b * 256 + i];
    }
    if (tid < 192) {
        int oc = tid / 3, k = tid % 3;
        wr[tid] = wpcS[oc * 9 + k * 3 + 0] + wpcS[oc * 9 + k * 3 + 1] + wpcS[oc * 9 + k * 3 + 2];
        wc[tid] = wpcS[oc * 9 + 0 + k] + wpcS[oc * 9 + 3 + k] + wpcS[oc * 9 + 6 + k];
    }
    __syncthreads();

    int p = tid & 63;                  // pooled position 0..63
    int gq = tid >> 6;                 // oc group 0..3
    int pi = p >> 3, pj = p & 7;
    int y0 = 2 * pi, x0 = 2 * pj;      // padded coords

    unsigned a[4][4];
    #pragma unroll
    for (int r = 0; r < 4; r++)
        #pragma unroll
        for (int q = 0; q < 4; q++)
            a[r][q] = sin_[y0 + r][x0 + q];

    // border flags: position (u,v)'s invalid tap row is dy = u?2:0 (iff flag),
    // invalid tap col is dx = v?2:0 (iff flag).
    bool rowI[2] = { pi == 0, pi == 7 };
    bool colI[2] = { pj == 0, pj == 7 };
    int nv32[2][2];
    #pragma unroll
    for (int u = 0; u < 2; u++)
        #pragma unroll
        for (int v = 0; v < 2; v++)
            nv32[u][v] = 32 * (3 - (rowI[u] ? 1 : 0)) * (3 - (colI[v] ? 1 : 0));

    for (int j = 0; j < 16; j++) {
        int oc = gq * 16 + j;
        const unsigned* wp = &swb[oc * 9];
        int mdot = -1000000;
        #pragma unroll
        for (int u = 0; u < 2; u++)
            #pragma unroll
            for (int v = 0; v < 2; v++) {
                int sum = 0;
                #pragma unroll
                for (int dy = 0; dy < 3; dy++)
                    #pragma unroll
                    for (int dx = 0; dx < 3; dx++)
                        sum += __popc(a[u + dy][v + dx] ^ wp[dy * 3 + dx]);
                int corr = 0;
                if (rowI[u]) corr += wr[oc * 3 + (u ? 2 : 0)];
                if (colI[v]) corr += wc[oc * 3 + (v ? 2 : 0)];
                if (rowI[u] && colI[v]) corr -= wpcS[oc * 9 + (u ? 6 : 0) + (v ? 2 : 0)];
                int d = nv32[u][v] + 2 * corr - 2 * sum;
                mdot = max(mdot, d);
            }
        bool bit = ((float)mdot + sb[oc]) > st[oc];
        unsigned bal = __ballot_sync(0xffffffffu, bit);
        if ((tid & 31) == 0) {
            int wrd = oc * 2 + (p >> 5);     // fc1 bit index = oc*64 + p
            g_act2[b * 128 + wrd] = bal;
        }
    }
}

// ---------------- fc1 (XNOR 4096-bit) + bn3 + sign ----------------
// Block: 8 samples x 512 ocs, 512 threads (one per oc). Force 2 blocks/SM.
__global__ __launch_bounds__(512, 2) void k_fc1(
    const float* __restrict__ bias, const float* __restrict__ g,
    const float* __restrict__ bb, const float* __restrict__ mn,
    const float* __restrict__ vr)
{
    __shared__ uint4 sa[8][32];
    int b0 = blockIdx.x * 8, tid = threadIdx.x;
    if (tid < 256) {
        int s = tid >> 5, k = tid & 31;
        const uint4* src = reinterpret_cast<const uint4*>(g_act2 + (b0 + s) * 128);
        sa[s][k] = src[k];
    }
    __syncthreads();

    int oc = tid;
    const uint4* wp = reinterpret_cast<const uint4*>(g_w1p + oc * 128);
    int acc[8] = {0, 0, 0, 0, 0, 0, 0, 0};
    #pragma unroll 2
    for (int k = 0; k < 32; k++) {
        uint4 w = wp[k];
        #pragma unroll
        for (int s = 0; s < 8; s++) {
            uint4 aa = sa[s][k];
            acc[s] += __popc(aa.x ^ w.x) + __popc(aa.y ^ w.y)
                    + __popc(aa.z ^ w.z) + __popc(aa.w ^ w.w);
        }
    }
    float bi = bias[oc];
    float th = mn[oc] - bb[oc] * sqrtf(vr[oc] + EPS) / g[oc];
    #pragma unroll
    for (int s = 0; s < 8; s++) {
        bool bit = ((float)(4096 - 2 * acc[s]) + bi) > th;
        unsigned bal = __ballot_sync(0xffffffffu, bit);
        if ((tid & 31) == 0) g_act3[(b0 + s) * 16 + (oc >> 5)] = bal;
    }
}

// ---------------- fc2 + bn4 + clip + fc3 + log_softmax ----------------
// One block per sample, 256 threads (one per fc2 oc).
__global__ __launch_bounds__(256, 2) void k_head(
    const float* __restrict__ fc2b, const float* __restrict__ g4,
    const float* __restrict__ b4, const float* __restrict__ m4,
    const float* __restrict__ v4, const float* __restrict__ fc3w,
    const float* __restrict__ fc3b, float* __restrict__ out)
{
    __shared__ __align__(16) unsigned a3[16];
    __shared__ float wred[8][10];
    __shared__ float lg[10];
    __shared__ float mx_s, ls_s;
    int b = blockIdx.x, tid = threadIdx.x;
    if (tid < 16) a3[tid] = g_act3[b * 16 + tid];
    __syncthreads();

    int o = tid;
    const uint4* wp = reinterpret_cast<const uint4*>(g_w2p + o * 16);
    const uint4* ap = reinterpret_cast<const uint4*>(a3);
    int acc = 0;
    #pragma unroll
    for (int k = 0; k < 4; k++) {
        uint4 w = wp[k];
        uint4 aa = ap[k];
        acc += __popc(aa.x ^ w.x) + __popc(aa.y ^ w.y)
             + __popc(aa.z ^ w.z) + __popc(aa.w ^ w.w);
    }
    float y = (float)(512 - 2 * acc) + fc2b[o];
    float inv = g4[o] / sqrtf(v4[o] + EPS);
    float val = y * inv + (b4[o] - m4[o] * inv);
    val = fminf(1.0f, fmaxf(-1.0f, val));

    float p[10];
    #pragma unroll
    for (int j = 0; j < 10; j++) p[j] = val * fc3w[j * 256 + o];
    #pragma unroll
    for (int j = 0; j < 10; j++) {
        float t = p[j];
        #pragma unroll
        for (int off = 16; off; off >>= 1) t += __shfl_xor_sync(0xffffffffu, t, off);
        if ((tid & 31) == 0) wred[tid >> 5][j] = t;
    }
    __syncthreads();
    if (tid < 10) {
        float s = 0.0f;
        #pragma unroll
        for (int w2 = 0; w2 < 8; w2++) s += wred[w2][tid];
        lg[tid] = s + fc3b[tid];
    }
    __syncthreads();
    if (tid == 0) {
        float mx = lg[0];
        #pragma unroll
        for (int j = 1; j < 10; j++) mx = fmaxf(mx, lg[j]);
        float ssum = 0.0f;
        #pragma unroll
        for (int j = 0; j < 10; j++) ssum += expf(lg[j] - mx);
        mx_s = mx;
        ls_s = logf(ssum);
    }
    __syncthreads();
    if (tid < 10) out[b * 10 + tid] = lg[tid] - mx_s - ls_s;
}

// ---------------- launch ----------------
extern "C" void kernel_launch(void* const* d_in, const int* in_sizes, int n_in,
                              void* d_out, int out_size) {
    const float* x    = (const float*)d_in[0];
    const float* c1w  = (const float*)d_in[1];
    const float* c1b  = (const float*)d_in[2];
    const float* bn1g = (const float*)d_in[3];
    const float* bn1b = (const float*)d_in[4];
    const float* bn1m = (const float*)d_in[5];
    const float* bn1v = (const float*)d_in[6];
    const float* c2w  = (const float*)d_in[7];
    const float* c2b  = (const float*)d_in[8];
    const float* bn2g = (const float*)d_in[9];
    const float* bn2b = (const float*)d_in[10];
    const float* bn2m = (const float*)d_in[11];
    const float* bn2v = (const float*)d_in[12];
    const float* fc1w = (const float*)d_in[13];
    const float* fc1b = (const float*)d_in[14];
    const float* bn3g = (const float*)d_in[15];
    const float* bn3b = (const float*)d_in[16];
    const float* bn3m = (const float*)d_in[17];
    const float* bn3v = (const float*)d_in[18];
    const float* fc2w = (const float*)d_in[19];
    const float* fc2b = (const float*)d_in[20];
    const float* bn4g = (const float*)d_in[21];
    const float* bn4b = (const float*)d_in[22];
    const float* bn4m = (const float*)d_in[23];
    const float* bn4v = (const float*)d_in[24];
    const float* fc3w = (const float*)d_in[25];
    const float* fc3b = (const float*)d_in[26];
    float* out = (float*)d_out;

    // total pack threads = 512*4096 + 256*512 + 64*9*32 = 2246656 = 8776 * 256
    k_pack<<<8776, 256>>>(fc1w, fc2w, c2w);
    k_conv1<<<BATCH, 256>>>(x, c1w, c1b, bn1g, bn1b, bn1m, bn1v);
    k_conv2<<<BATCH, 256>>>(c2b, bn2g, bn2b, bn2m, bn2v);
    k_fc1<<<BATCH / 8, 512>>>(fc1b, bn3g, bn3b, bn3m, bn3v);
    k_head<<<BATCH, 256>>>(fc2b, bn4g, bn4b, bn4m, bn4v, fc3w, fc3b, out);
}